// round 11
// baseline (speedup 1.0000x reference)
#include <cuda_runtime.h>
#include <cuda_bf16.h>
#include <math_constants.h>

// Problem constants
#define BATCH 16
#define SEQ   4096
#define EMB   2048
#define WIN   64
#define NWIN  (SEQ - WIN + 1)     // 4033

#define ROWS_PER_BLOCK 8
#define BLOCKS_PER_BATCH (SEQ / ROWS_PER_BLOCK)   // 512
#define ELEMS_PER_THREAD 16                       // phase B: 4096 / 256

// Scratch (static device arrays: allocation-free, zero-initialized at load)
__device__ float        g_scores[BATCH * SEQ];
__device__ unsigned int g_cnt[BATCH];   // per-batch completed-block counters

// ---------------------------------------------------------------------------
// Fused kernel, last-arriving-block finisher:
//  Phase A (all 8192 blocks): one warp per row, mask-skip dot(x,W)+b  (R7 path)
//  Arrival: ONE fence + atomic per block (per-batch counter)
//  Phase B (the block that completes its batch): scan + window max -> out[b]
// ---------------------------------------------------------------------------
__global__ __launch_bounds__(256) void fused_kernel(
    const float* __restrict__ x,
    const int*   __restrict__ mask,   // bool mask coerced to int32 by harness
    const float* __restrict__ W,
    const float* __restrict__ bias,
    float*       __restrict__ out)
{
    __shared__ float buf[SEQ];      // 16 KB union: W in [0..EMB) (phase A),
                                    // scores->prefix sums in [0..SEQ) (phase B)
    __shared__ float wtot[8];
    __shared__ float red[8];
    __shared__ unsigned int sFin;

    const int tid  = threadIdx.x;
    const int wid  = tid >> 5;
    const int lane = tid & 31;
    const int b    = blockIdx.x / BLOCKS_PER_BATCH;
    const int row  = blockIdx.x * ROWS_PER_BLOCK + wid;

    // Stage W into shared
    for (int i = tid; i < EMB; i += 256)
        buf[i] = W[i];
    __syncthreads();

    // ---------------- Phase A: score this block's 8 rows --------------------
    {
        const int m = mask[row];
        if (m == 0) {
            if (lane == 0) g_scores[row] = 0.0f;
        } else {
            const float4* __restrict__ xr =
                reinterpret_cast<const float4*>(x + (size_t)row * EMB);
            const float4* __restrict__ wr = reinterpret_cast<const float4*>(buf);

            float acc = 0.0f;
            #pragma unroll
            for (int h = 0; h < 2; h++) {
                float4 a[8];
                #pragma unroll
                for (int j = 0; j < 8; j++)
                    a[j] = __ldcs(&xr[lane + (h * 8 + j) * 32]);
                #pragma unroll
                for (int j = 0; j < 8; j++) {
                    float4 w = wr[lane + (h * 8 + j) * 32];
                    acc = fmaf(a[j].x, w.x, acc);
                    acc = fmaf(a[j].y, w.y, acc);
                    acc = fmaf(a[j].z, w.z, acc);
                    acc = fmaf(a[j].w, w.w, acc);
                }
            }

            #pragma unroll
            for (int o = 16; o > 0; o >>= 1)
                acc += __shfl_xor_sync(0xffffffffu, acc, o);

            if (lane == 0)
                g_scores[row] = acc + bias[0];
        }
    }

    // ---------------- Arrival: one fence + atomic per block -----------------
    __syncthreads();                 // all 8 warps' stores issued
    if (tid == 0) {
        __threadfence();             // publish this block's score stores
        unsigned int r = atomicAdd(&g_cnt[b], 1u);
        sFin = (r == BLOCKS_PER_BATCH - 1) ? 1u : 0u;
        if (sFin) __threadfence();   // acquire: order count vs score reads
    }
    __syncthreads();
    if (!sFin) return;

    // ---------------- Phase B: finisher for batch b --------------------------
    // Load this batch's 4096 scores (L2-hot) into shared (16 floats/thread)
    {
        const float4* src = reinterpret_cast<const float4*>(g_scores + b * SEQ);
        float4*       dst = reinterpret_cast<float4*>(buf);
        #pragma unroll
        for (int i = 0; i < SEQ / 4 / 256; i++)   // 4 iters
            dst[tid + i * 256] = __ldcg(&src[tid + i * 256]);
    }
    __syncthreads();

    // Block-wide inclusive prefix scan, 16 elems/thread, in place.
    float p[ELEMS_PER_THREAD];
    {
        const int base = tid * ELEMS_PER_THREAD;
        float run = 0.0f;
        #pragma unroll
        for (int j = 0; j < ELEMS_PER_THREAD; j++) {
            run += buf[base + j];
            p[j] = run;
        }
        // Warp inclusive scan of thread totals
        float t = run;
        #pragma unroll
        for (int o = 1; o < 32; o <<= 1) {
            float u = __shfl_up_sync(0xffffffffu, t, o);
            if (lane >= o) t += u;
        }
        float warpExcl = t - run;
        if (lane == 31) wtot[wid] = t;
        __syncthreads();

        // Scan the 8 warp totals (warp 0, lanes 0..7)
        if (wid == 0 && lane < 8) {
            float wt = wtot[lane];
            #pragma unroll
            for (int o = 1; o < 8; o <<= 1) {
                float u = __shfl_up_sync(0xffu, wt, o);
                if (lane >= o) wt += u;
            }
            wtot[lane] = wt - wtot[lane];   // exclusive warp offsets
        }
        __syncthreads();

        const float off = wtot[wid] + warpExcl;
        #pragma unroll
        for (int j = 0; j < ELEMS_PER_THREAD; j++)
            buf[base + j] = off + p[j];     // inclusive cumsum
    }
    __syncthreads();

    // Window sums: w(i) = cs[i+WIN-1] - (i>0 ? cs[i-1] : 0), i in 16t..16t+15
    const int i0 = tid * ELEMS_PER_THREAD;
    float best = -CUDART_INF_F;
    #pragma unroll
    for (int j = 0; j < ELEMS_PER_THREAD; j++) {
        int i = i0 + j;
        if (i < NWIN) {
            float hi = buf[i + WIN - 1];
            float lo = (i > 0) ? buf[i - 1] : 0.0f;
            best = fmaxf(best, hi - lo);
        }
    }

    // Block max reduce (8 warps)
    #pragma unroll
    for (int o = 16; o > 0; o >>= 1)
        best = fmaxf(best, __shfl_xor_sync(0xffffffffu, best, o));
    if (lane == 0) red[wid] = best;
    __syncthreads();

    if (tid == 0) {
        float v = red[0];
        #pragma unroll
        for (int i = 1; i < 8; i++)
            v = fmaxf(v, red[i]);
        out[b] = v * (1.0f / (float)WIN);
        g_cnt[b] = 0u;               // reset for next graph replay
    }
}

// ---------------------------------------------------------------------------
// Launch: single kernel, 8192 blocks (hardware scheduler load-balances)
// ---------------------------------------------------------------------------
extern "C" void kernel_launch(void* const* d_in, const int* in_sizes, int n_in,
                              void* d_out, int out_size)
{
    const float* x    = (const float*)d_in[0];
    const int*   mask = (const int*)d_in[1];
    const float* W    = (const float*)d_in[2];
    const float* bias = (const float*)d_in[3];
    float*       out  = (float*)d_out;

    fused_kernel<<<BATCH * BLOCKS_PER_BATCH, 256>>>(x, mask, W, bias, out);
}

// round 13
// speedup vs baseline: 1.1394x; 1.1394x over previous
#include <cuda_runtime.h>
#include <cuda_bf16.h>
#include <math_constants.h>

// Problem constants
#define BATCH 16
#define SEQ   4096
#define EMB   2048
#define WIN   64
#define NWIN  (SEQ - WIN + 1)     // 4033

#define SLICES 8
#define STARTS_PER_SLICE (SEQ / SLICES)   // 512

// Scratch (static device arrays: allocation-free, zero-initialized at load)
__device__ float        g_scores[BATCH * SEQ];
__device__ unsigned int g_bmax[BATCH];   // encoded per-batch max (0 = -inf)
__device__ unsigned int g_cnt[BATCH];    // per-batch slice arrivals

// Order-preserving float <-> uint encoding (monotone for all non-NaN floats)
__device__ __forceinline__ unsigned int enc_f32(float f) {
    unsigned int u = __float_as_uint(f);
    return (u & 0x80000000u) ? ~u : (u | 0x80000000u);
}
__device__ __forceinline__ float dec_f32(unsigned int e) {
    unsigned int u = (e & 0x80000000u) ? (e ^ 0x80000000u) : ~e;
    return __uint_as_float(u);
}

// ---------------------------------------------------------------------------
// Kernel 1 (R9 roofline version, untouched):
// s[b,t] = mask[b,t] ? dot(x[b,t,:], W) + bias : 0
// One warp per row, masked rows skip the 8KB read, streaming loads MLP=8.
// ---------------------------------------------------------------------------
__global__ __launch_bounds__(256) void score_kernel(
    const float* __restrict__ x,
    const int*   __restrict__ mask,   // bool mask coerced to int32 by harness
    const float* __restrict__ W,
    const float* __restrict__ bias)
{
    __shared__ float sW[EMB];
    for (int i = threadIdx.x; i < EMB; i += blockDim.x)
        sW[i] = W[i];
    __syncthreads();

    const int warp = blockIdx.x * 8 + (threadIdx.x >> 5);
    const int lane = threadIdx.x & 31;

    const int m = mask[warp];
    if (m == 0) {
        if (lane == 0) g_scores[warp] = 0.0f;
        return;
    }

    const float4* __restrict__ xr = reinterpret_cast<const float4*>(x + (size_t)warp * EMB);
    const float4* __restrict__ wr = reinterpret_cast<const float4*>(sW);

    float acc = 0.0f;
    #pragma unroll
    for (int h = 0; h < 2; h++) {
        float4 a[8];
        #pragma unroll
        for (int j = 0; j < 8; j++)
            a[j] = __ldcs(&xr[lane + (h * 8 + j) * 32]);
        #pragma unroll
        for (int j = 0; j < 8; j++) {
            float4 w = wr[lane + (h * 8 + j) * 32];
            acc = fmaf(a[j].x, w.x, acc);
            acc = fmaf(a[j].y, w.y, acc);
            acc = fmaf(a[j].z, w.z, acc);
            acc = fmaf(a[j].w, w.w, acc);
        }
    }

    #pragma unroll
    for (int o = 16; o > 0; o >>= 1)
        acc += __shfl_xor_sync(0xffffffffu, acc, o);

    if (lane == 0)
        g_scores[warp] = acc + bias[0];
}

// ---------------------------------------------------------------------------
// Kernel 2 (PDL): 128 blocks = 16 batches x 8 slices, 128 threads.
// Slice-local rolling window sums -> block max -> per-batch atomicMax.
// 8th arriver of each batch decodes and writes out[b].
// ---------------------------------------------------------------------------
__global__ __launch_bounds__(128) void window_max_kernel(float* __restrict__ out)
{
    __shared__ float s[STARTS_PER_SLICE + WIN];   // 576 floats
    __shared__ float red[4];

    const int tid  = threadIdx.x;
    const int lane = tid & 31;
    const int wid  = tid >> 5;
    const int b    = blockIdx.x >> 3;       // /SLICES
    const int sl   = blockIdx.x & 7;        // %SLICES
    const int base = sl * STARTS_PER_SLICE;

    // Pre-dependency address math, then gate on primary completion
    const float* src = g_scores + b * SEQ;
    cudaGridDependencySynchronize();

    // Stage slice scores (+64 halo) into shared; float4 loads.
    // 576/4 = 144 float4; 128 threads -> 1 full iter + partial second.
    {
        const float4* s4 = reinterpret_cast<const float4*>(src + base);
        float4*       d4 = reinterpret_cast<float4*>(s);
        d4[tid] = __ldcg(&s4[tid]);
        int i2 = tid + 128;
        if (i2 < (STARTS_PER_SLICE + WIN) / 4) {
            int gidx = base + i2 * 4;
            if (gidx < SEQ) {
                d4[i2] = __ldcg(&s4[i2]);
            } else {
                float4 z = {0.0f, 0.0f, 0.0f, 0.0f};
                d4[i2] = z;
            }
        }
    }
    __syncthreads();

    // Thread t covers starts base+4t .. base+4t+3 via rolling sum
    const int start0 = base + tid * 4;
    float best = -CUDART_INF_F;
    if (start0 < NWIN) {
        const float4* sv = reinterpret_cast<const float4*>(s) + tid;
        float sum = 0.0f;
        #pragma unroll
        for (int k = 0; k < WIN / 4; k++) {
            float4 v = sv[k];
            sum += (v.x + v.y) + (v.z + v.w);
        }
        best = sum;
        #pragma unroll
        for (int j = 1; j < 4; j++) {
            int i = start0 + j;
            if (i < NWIN) {
                int li = tid * 4 + j;
                sum += s[li + WIN - 1] - s[li - 1];
                best = fmaxf(best, sum);
            }
        }
    }

    // Block max reduce (4 warps)
    #pragma unroll
    for (int o = 16; o > 0; o >>= 1)
        best = fmaxf(best, __shfl_xor_sync(0xffffffffu, best, o));
    if (lane == 0) red[wid] = best;
    __syncthreads();

    if (tid == 0) {
        float m = fmaxf(fmaxf(red[0], red[1]), fmaxf(red[2], red[3]));
        atomicMax(&g_bmax[b], enc_f32(m));
        __threadfence();                         // order max before arrival
        unsigned int r = atomicAdd(&g_cnt[b], 1u);
        if (r == SLICES - 1) {                   // last slice of batch b
            __threadfence();                     // acquire all 8 maxes
            unsigned int e = atomicAdd(&g_bmax[b], 0u);
            out[b] = dec_f32(e) * (1.0f / (float)WIN);
            g_cnt[b]  = 0u;                      // reset for next replay
            g_bmax[b] = 0u;
        }
    }
}

// ---------------------------------------------------------------------------
// Launch: kernel 1 normally, kernel 2 via PDL
// ---------------------------------------------------------------------------
extern "C" void kernel_launch(void* const* d_in, const int* in_sizes, int n_in,
                              void* d_out, int out_size)
{
    const float* x    = (const float*)d_in[0];
    const int*   mask = (const int*)d_in[1];
    const float* W    = (const float*)d_in[2];
    const float* bias = (const float*)d_in[3];
    float*       out  = (float*)d_out;

    score_kernel<<<BATCH * SEQ / 8, 256>>>(x, mask, W, bias);

    cudaLaunchConfig_t cfg = {};
    cfg.gridDim  = dim3(BATCH * SLICES, 1, 1);
    cfg.blockDim = dim3(128, 1, 1);
    cfg.dynamicSmemBytes = 0;
    cfg.stream = 0;
    cudaLaunchAttribute attrs[1];
    attrs[0].id = cudaLaunchAttributeProgrammaticStreamSerialization;
    attrs[0].val.programmaticStreamSerializationAllowed = 1;
    cfg.attrs = attrs;
    cfg.numAttrs = 1;
    cudaLaunchKernelEx(&cfg, window_max_kernel, out);
}